// round 15
// baseline (speedup 1.0000x reference)
#include <cuda_runtime.h>
#include <cuda_fp16.h>
#include <math.h>
#include <float.h>
#include <stdint.h>

#define BB   8
#define NN   515
#define DD   1024
#define HH   8
#define LL   4
#define FFD  4096
#define NKV  516
#define MM   (BB*NN)
#define KTP  552
#define EPSL 1e-5f

// ---------------- scratch ----------------
__device__ float g_X  [MM*DD];
__device__ float g_QKV[MM*640];
__device__ float g_Kt [BB*64*KTP];
__device__ float g_V  [(BB*NKV + 32)*64];
__device__ float g_T  [MM*DD];
__device__ float g_bias[HH*NN*NKV + 64];
__device__ float g_bqkv[LL*640];
__device__ float g_cos[NN*16];
__device__ float g_sin[NN*16];
__device__ __half g_XNh[MM*DD],  g_XNl[MM*DD];
__device__ __half g_Oh [MM*512], g_Ol [MM*512];
__device__ __half g_AGh[(size_t)MM*FFD], g_AGl[(size_t)MM*FFD];
__device__ __half g_WqkvT[LL*640*DD];
__device__ __half g_WoT  [LL*DD*512];
__device__ __half g_Wff1T[(size_t)LL*2*FFD*DD];
__device__ __half g_Wff2T[(size_t)LL*DD*FFD];
__device__ __half g_WprojT[DD*DD];

// ---------------- small helpers ----------------
__device__ __forceinline__ uint32_t smem_u32(const void* p) {
    uint32_t a;
    asm("{ .reg .u64 t; cvta.to.shared.u64 t, %1; cvt.u32.u64 %0, t; }" : "=r"(a) : "l"(p));
    return a;
}
__device__ __forceinline__ void cp16(uint32_t dst, const void* src, bool pred) {
    int sz = pred ? 16 : 0;
    asm volatile("cp.async.cg.shared.global [%0], [%1], 16, %2;\n" :: "r"(dst), "l"(src), "r"(sz));
}
__device__ __forceinline__ void cp_commit() {
    asm volatile("cp.async.commit_group;\n" ::: "memory");
}
template<int N>
__device__ __forceinline__ void cp_wait() {
    asm volatile("cp.async.wait_group %0;\n" :: "n"(N) : "memory");
}
__device__ __forceinline__ void ldsm4(uint32_t* r, uint32_t addr) {
    asm volatile("ldmatrix.sync.aligned.m8n8.x4.shared.b16 {%0,%1,%2,%3}, [%4];"
                 : "=r"(r[0]), "=r"(r[1]), "=r"(r[2]), "=r"(r[3]) : "r"(addr));
}
__device__ __forceinline__ void mma_f16(float* c, const uint32_t* a, const uint32_t* b) {
    asm volatile(
        "mma.sync.aligned.m16n8k16.row.col.f32.f16.f16.f32 "
        "{%0,%1,%2,%3}, {%4,%5,%6,%7}, {%8,%9}, {%0,%1,%2,%3};"
        : "+f"(c[0]), "+f"(c[1]), "+f"(c[2]), "+f"(c[3])
        : "r"(a[0]), "r"(a[1]), "r"(a[2]), "r"(a[3]), "r"(b[0]), "r"(b[1]));
}

// ===== mma.sync 2-term fp16-split GEMM: C[M,N] = A[M,K] @ B[N,K]^T ========
// CTA tile 64x128, 256 threads (8 warps 2x4), warp tile 32x32, 2-stage,
// k-chunk 64 (stride-72 rows). 3 CTAs/SM (24 warps) via launch_bounds(256,3).
// Per-accumulator MMA order identical to rounds 8-14 -> bit-identical.
#define A_HB      (64*72*2)             // 9216 B per A tile (hi or lo)
#define B_HB      (128*72*2)            // 18432 B
#define STG       (2*A_HB + B_HB)       // 36864 B
#define SMEM_TOT  (2*STG)               // 73728 B

__global__ __launch_bounds__(256, 3)
void bgemm_kernel(const __half* __restrict__ Ah, const __half* __restrict__ Al,
                  const __half* __restrict__ Bh,
                  const float* __restrict__ bias, float* __restrict__ C,
                  __half* __restrict__ outh, __half* __restrict__ outl,
                  int M, int N, int K, int mode)
{
    extern __shared__ char smem[];
    const uint32_t sbase = smem_u32(smem);

    const int tid  = threadIdx.x;
    const int lane = tid & 31;
    const int warp = tid >> 5;
    const int warp_row = (warp & 1) * 32;     // 2 warps down M (64)
    const int warp_col = (warp >> 1) * 32;    // 4 warps across N (128)
    const int block_row = blockIdx.y * 64;
    const int block_col = blockIdx.x * 128;
    const int KC = K >> 6;

    const int aRow  = (lane & 15);
    const int aColH = (lane >> 4) << 3;
    const int bRow  = ((lane >> 4) << 3) + (lane & 7);
    const int bColH = ((lane >> 3) & 1) << 3;

    float acc[2][4][4];
    #pragma unroll
    for (int a = 0; a < 2; a++)
        #pragma unroll
        for (int b = 0; b < 4; b++)
            #pragma unroll
            for (int c = 0; c < 4; c++) acc[a][b][c] = 0.f;

    // loader: 2048 16B-units per chunk (Ah 512, Al 512, B 1024), 8/thread
    auto load_chunk = [&](int s, int k0) {
        const uint32_t st = sbase + s * STG;
        #pragma unroll
        for (int i = 0; i < 8; i++) {
            const int u = tid + i * 256;
            if (u < 1024) {
                const int v = u & 511;
                const int row = v >> 3, cc = (v & 7) * 8;
                const int gr = block_row + row;
                const __half* src = ((u < 512) ? Ah : Al) + (size_t)gr * K + k0 + cc;
                cp16(st + ((u < 512) ? 0 : A_HB) + (row * 72 + cc) * 2, src, gr < M);
            } else {
                const int v = u - 1024;
                const int row = v >> 3, cc = (v & 7) * 8;
                cp16(st + 2 * A_HB + (row * 72 + cc) * 2,
                     Bh + (size_t)(block_col + row) * K + k0 + cc, true);
            }
        }
        cp_commit();
    };

    load_chunk(0, 0);

    for (int c = 0; c < KC; ++c) {
        const int s = c & 1;
        if (c + 1 < KC) {
            load_chunk(s ^ 1, (c + 1) << 6);
            cp_wait<1>();
        } else {
            cp_wait<0>();
        }
        __syncthreads();

        const uint32_t st = sbase + s * STG;
        #pragma unroll
        for (int ks = 0; ks < 4; ks++) {
            const int k0s = ks << 4;
            uint32_t ah[2][4], al[2][4], bh[2][4];
            #pragma unroll
            for (int mt = 0; mt < 2; mt++) {
                const uint32_t addr = st + ((warp_row + mt * 16 + aRow) * 72 + k0s + aColH) * 2;
                ldsm4(ah[mt], addr);
                ldsm4(al[mt], addr + A_HB);
            }
            #pragma unroll
            for (int np = 0; np < 2; np++) {
                const uint32_t addr = st + 2 * A_HB +
                    ((warp_col + np * 16 + bRow) * 72 + k0s + bColH) * 2;
                ldsm4(bh[np], addr);
            }
            #pragma unroll
            for (int mt = 0; mt < 2; mt++)
                #pragma unroll
                for (int nt = 0; nt < 4; nt++)
                    mma_f16(acc[mt][nt], ah[mt], &bh[nt >> 1][(nt & 1) * 2]);
            #pragma unroll
            for (int mt = 0; mt < 2; mt++)
                #pragma unroll
                for (int nt = 0; nt < 4; nt++)
                    mma_f16(acc[mt][nt], al[mt], &bh[nt >> 1][(nt & 1) * 2]);
        }
        __syncthreads();
    }

    const int gid = lane >> 2;
    const int tig = lane & 3;
    #pragma unroll
    for (int mt = 0; mt < 2; mt++) {
        int r0 = block_row + warp_row + mt * 16 + gid;
        #pragma unroll
        for (int half = 0; half < 2; half++) {
            int r = r0 + half * 8;
            if (r >= M) continue;
            #pragma unroll
            for (int nt = 0; nt < 4; nt++) {
                int col = block_col + warp_col + nt * 8 + 2 * tig;
                float v0 = acc[mt][nt][half * 2 + 0];
                float v1 = acc[mt][nt][half * 2 + 1];
                if (mode == 2) {
                    float v = v0 * v1 / (1.f + __expf(-v1));
                    __half h = __float2half_rn(v);
                    size_t o = (size_t)r * (N >> 1) + (col >> 1);
                    outh[o] = h;
                    outl[o] = __float2half_rn(v - __half2float(h));
                } else {
                    if (bias) { v0 += bias[col]; v1 += bias[col + 1]; }
                    float* cp = C + (size_t)r * N + col;
                    if (mode == 1) { cp[0] += v0; cp[1] += v1; }
                    else           { cp[0]  = v0; cp[1]  = v1; }
                }
            }
        }
    }
}

// -------- fused weight transpose (fp16, one launch, tight grid) ------------
struct WDesc { const float* W; __half* Th; int K; int N; int glu; };
struct WTable { WDesc d[21]; int off[22]; };

__global__ void wsplit_all_kernel(WTable tab) {
    const int bid = blockIdx.x;
    int wi = 0;
    while (bid >= tab.off[wi + 1]) wi++;
    const WDesc w = tab.d[wi];
    const int t = bid - tab.off[wi];
    const int tilesN = w.N >> 5;
    const int nb = (t % tilesN) * 32;
    const int kb = (t / tilesN) * 32;
    __shared__ float sm[32][33];
    const int x = threadIdx.x, y = threadIdx.y;
    const int n0 = nb + x;
    const int sc = w.glu ? ((n0 & 1) * FFD + (n0 >> 1)) : n0;
    #pragma unroll
    for (int j = 0; j < 32; j += 8)
        sm[y + j][x] = w.W[(size_t)(kb + y + j) * w.N + sc];
    __syncthreads();
    #pragma unroll
    for (int j = 0; j < 32; j += 8)
        w.Th[(size_t)(nb + y + j) * w.K + kb + x] = __float2half_rn(sm[x][y + j]);
}

// ---------------- reductions ----------------
__device__ __forceinline__ float warpReduceSum(float v) {
    #pragma unroll
    for (int o = 16; o > 0; o >>= 1) v += __shfl_xor_sync(0xffffffffu, v, o);
    return v;
}
__device__ __forceinline__ float warpReduceMax(float v) {
    #pragma unroll
    for (int o = 16; o > 0; o >>= 1) v = fmaxf(v, __shfl_xor_sync(0xffffffffu, v, o));
    return v;
}
__device__ __forceinline__ float blockReduceSum(float v) {
    __shared__ float sh[8];
    int lane = threadIdx.x & 31, w = threadIdx.x >> 5;
    v = warpReduceSum(v);
    __syncthreads();
    if (lane == 0) sh[w] = v;
    __syncthreads();
    if (w == 0) {
        float t = (lane < 8) ? sh[lane] : 0.f;
        t = warpReduceSum(t);
        if (lane == 0) sh[0] = t;
    }
    __syncthreads();
    return sh[0];
}
__device__ __forceinline__ float blockReduceMax(float v) {
    __shared__ float sh[8];
    int lane = threadIdx.x & 31, w = threadIdx.x >> 5;
    v = warpReduceMax(v);
    __syncthreads();
    if (lane == 0) sh[w] = v;
    __syncthreads();
    if (w == 0) {
        float t = (lane < 8) ? sh[lane] : -FLT_MAX;
        t = warpReduceMax(t);
        if (lane == 0) sh[0] = t;
    }
    __syncthreads();
    return sh[0];
}

// -------- LayerNorm: mode 0 split(LN(in)*g), mode 2 stable split ------------
__global__ __launch_bounds__(256)
void ln_kernel(const float* __restrict__ in, const float* __restrict__ g,
               __half* __restrict__ outh, __half* __restrict__ outl, int mode)
{
    const int row = blockIdx.x;
    const float* xr = in + (size_t)row * DD;
    const int t = threadIdx.x;
    float v[4];
    #pragma unroll
    for (int i = 0; i < 4; i++) v[i] = xr[t + i * 256];
    if (mode == 2) {
        float lm = -FLT_MAX;
        #pragma unroll
        for (int i = 0; i < 4; i++) lm = fmaxf(lm, v[i]);
        float inv = 1.f / blockReduceMax(lm);
        #pragma unroll
        for (int i = 0; i < 4; i++) v[i] *= inv;
    }
    float s = 0.f;
    #pragma unroll
    for (int i = 0; i < 4; i++) s += v[i];
    float mean = blockReduceSum(s) * (1.f / DD);
    float vs = 0.f;
    #pragma unroll
    for (int i = 0; i < 4; i++) { float d = v[i] - mean; vs += d * d; }
    float rstd = rsqrtf(blockReduceSum(vs) * (1.f / DD) + EPSL);
    #pragma unroll
    for (int i = 0; i < 4; i++) {
        int c = t + i * 256;
        float y = (v[i] - mean) * rstd * g[c];
        size_t idx = (size_t)row * DD + c;
        __half h = __float2half_rn(y);
        outh[idx] = h;
        outl[idx] = __float2half_rn(y - __half2float(h));
    }
}

// -------- fused: X = resid + LN(T)*g1 ; split(LN(X)*g2) --------------------
__global__ __launch_bounds__(256)
void ln2_kernel(const float* __restrict__ T, const float* __restrict__ resid,
                const float* __restrict__ g1, const float* __restrict__ g2,
                float* __restrict__ X, __half* __restrict__ outh,
                __half* __restrict__ outl)
{
    const int row = blockIdx.x;
    const int t = threadIdx.x;
    const float* tr = T + (size_t)row * DD;
    const float* rr = resid + (size_t)row * DD;
    float v[4];
    #pragma unroll
    for (int i = 0; i < 4; i++) v[i] = tr[t + i * 256];
    float s = 0.f;
    #pragma unroll
    for (int i = 0; i < 4; i++) s += v[i];
    float mean = blockReduceSum(s) * (1.f / DD);
    float vs = 0.f;
    #pragma unroll
    for (int i = 0; i < 4; i++) { float d = v[i] - mean; vs += d * d; }
    float rstd = rsqrtf(blockReduceSum(vs) * (1.f / DD) + EPSL);
    float x[4];
    #pragma unroll
    for (int i = 0; i < 4; i++) {
        int c = t + i * 256;
        x[i] = rr[c] + (v[i] - mean) * rstd * g1[c];
        X[(size_t)row * DD + c] = x[i];
    }
    float s2 = 0.f;
    #pragma unroll
    for (int i = 0; i < 4; i++) s2 += x[i];
    float mean2 = blockReduceSum(s2) * (1.f / DD);
    float vs2 = 0.f;
    #pragma unroll
    for (int i = 0; i < 4; i++) { float d = x[i] - mean2; vs2 += d * d; }
    float rstd2 = rsqrtf(blockReduceSum(vs2) * (1.f / DD) + EPSL);
    #pragma unroll
    for (int i = 0; i < 4; i++) {
        int c = t + i * 256;
        float y = (x[i] - mean2) * rstd2 * g2[c];
        size_t idx = (size_t)row * DD + c;
        __half h = __float2half_rn(y);
        outh[idx] = h;
        outl[idx] = __float2half_rn(y - __half2float(h));
    }
}

// ---------------- precompute: rope + rel-pos bias + qkv bias ---------------
__global__ void precompute_kernel(const float* __restrict__ emb,
                                  const float* __restrict__ bkv) {
    int idx = blockIdx.x * blockDim.x + threadIdx.x;
    if (idx < NN * 16) {
        int p = idx >> 4, i = idx & 15;
        float fr = (float)p * powf(10000.f, -(float)(2 * i) / 32.f);
        g_cos[idx] = cosf(fr);
        g_sin[idx] = sinf(fr);
    }
    if (idx < LL * 640) {
        int c = idx % 640;
        g_bqkv[idx] = (c < 512) ? 0.f : bkv[(idx / 640) * 128 + c - 512];
    }
    if (idx >= NN * NKV) return;
    int i = idx / NKV, j = idx % NKV;
    int nn = max(i - j, 0);
    int bucket;
    if (nn < 16) bucket = nn;
    else {
        int vl = 16 + (int)(logf((float)nn * (1.f / 16.f)) / logf(8.f) * 16.f);
        bucket = min(vl, 31);
    }
    #pragma unroll
    for (int h = 0; h < HH; h++)
        g_bias[((size_t)h * NN + i) * NKV + j] = emb[bucket * HH + h];
}

// ---------------- kv post: rotary+norm k -> Kt, copy v ----------------------
__global__ __launch_bounds__(256)
void kvpost_kernel(const float* __restrict__ nullkv) {
    int gw   = (blockIdx.x * blockDim.x + threadIdx.x) >> 5;
    int lane = threadIdx.x & 31;
    if (gw >= BB * NKV) return;
    int b = gw / NKV, j = gw % NKV;
    float k0, k1, v0, v1;
    if (j == 0) {
        k0 = nullkv[lane];      k1 = nullkv[lane + 32];
        v0 = nullkv[64 + lane]; v1 = nullkv[96 + lane];
    } else {
        int pos = j - 1;
        const float* kv = g_QKV + ((size_t)(b * NN + pos)) * 640 + 512;
        k0 = kv[lane];      k1 = kv[lane + 32];
        v0 = kv[64 + lane]; v1 = kv[96 + lane];
        float c = g_cos[pos * 16 + (lane >> 1)];
        float s = g_sin[pos * 16 + (lane >> 1)];
        float part = __shfl_xor_sync(0xffffffffu, k0, 1);
        k0 = (lane & 1) ? fmaf(k0, c, part * s) : fmaf(k0, c, -part * s);
    }
    float inv = 4.f * rsqrtf(warpReduceSum(k0 * k0 + k1 * k1));
    g_Kt[((size_t)b * 64 + lane)      * KTP + j] = k0 * inv;
    g_Kt[((size_t)b * 64 + lane + 32) * KTP + j] = k1 * inv;
    size_t o = ((size_t)(b * NKV + j)) * 64;
    g_V[o + lane] = v0;
    g_V[o + lane + 32] = v1;
}

// -------- attention: block per (b,i), warp per head; smem K/V staging ------
#define AKW   36
#define ASTG  (64*AKW + 32*64)
__global__ __launch_bounds__(256)
void attn_kernel() {
    __shared__ float sbuf[2 * ASTG];
    const int bi = blockIdx.x;
    const int b = bi / NN, i = bi % NN;
    const int h = threadIdx.x >> 5;
    const int lane = threadIdx.x & 31;

    const float* qp = g_QKV + ((size_t)(b * NN + i)) * 640 + h * 64;
    float q0 = qp[lane], q1 = qp[lane + 32];
    {
        float c = g_cos[i * 16 + (lane >> 1)];
        float s = g_sin[i * 16 + (lane >> 1)];
        float part = __shfl_xor_sync(0xffffffffu, q0, 1);
        q0 = (lane & 1) ? fmaf(q0, c, part * s) : fmaf(q0, c, -part * s);
        float inv = 4.f * rsqrtf(warpReduceSum(q0 * q0 + q1 * q1));
        q0 *= inv; q1 *= inv;
    }
    const float* Ktb = g_Kt + (size_t)b * 64 * KTP;
    const float* Vb  = g_V  + (size_t)b * NKV * 64;
    const float* bp  = g_bias + ((size_t)h * NN + i) * NKV;
    const uint32_t sb = smem_u32(sbuf);

    auto load_blk = [&](int s, int j0) {
        const uint32_t st = sb + s * (ASTG * 4);
        #pragma unroll
        for (int t = 0; t < 4; t++) {
            const int u = threadIdx.x + t * 256;
            if (u < 512) {
                const int d = u >> 3, uu = (u & 7) * 4;
                cp16(st + (d * AKW + uu) * 4, Ktb + (size_t)d * KTP + j0 + uu, true);
            } else {
                const int v = u - 512;
                const int row = v >> 4, uu = (v & 15) * 4;
                cp16(st + (64 * AKW + row * 64 + uu) * 4,
                     Vb + (size_t)(j0 + row) * 64 + uu, true);
            }
        }
        cp_commit();
    };

    const int jmax = i + 1;
    const int NBK = (jmax >> 5) + 1;
    load_blk(0, 0);

    float lsum = 0.f, o0 = 0.f, o1 = 0.f;
    for (int blk = 0; blk < NBK; blk++) {
        if (blk + 1 < NBK) {
            load_blk((blk + 1) & 1, (blk + 1) << 5);
            cp_wait<1>();
        } else {
            cp_wait<0>();
        }
        __syncthreads();

        const float* sK = sbuf + (blk & 1) * ASTG;
        const float* sV = sK + 64 * AKW;
        const int j = (blk << 5) + lane;

        float a0 = 0.f, a1 = 0.f, a2 = 0.f, a3 = 0.f;
        #pragma unroll
        for (int d = 0; d < 32; d += 4) {
            a0 = fmaf(__shfl_sync(0xffffffffu, q0, d    ), sK[(d    ) * AKW + lane], a0);
            a1 = fmaf(__shfl_sync(0xffffffffu, q0, d + 1), sK[(d + 1) * AKW + lane], a1);
            a2 = fmaf(__shfl_sync(0xffffffffu, q0, d + 2), sK[(d + 2) * AKW + lane], a2);
            a3 = fmaf(__shfl_sync(0xffffffffu, q0, d + 3), sK[(d + 3) * AKW + lane], a3);
        }
        #pragma unroll
        for (int d = 0; d < 32; d += 4) {
            a0 = fmaf(__shfl_sync(0xffffffffu, q1, d    ), sK[(d + 32) * AKW + lane], a0);
            a1 = fmaf(__shfl_sync(0xffffffffu, q1, d + 1), sK[(d + 33) * AKW + lane], a1);
            a2 = fmaf(__shfl_sync(0xffffffffu, q1, d + 2), sK[(d + 34) * AKW + lane], a2);
            a3 = fmaf(__shfl_sync(0xffffffffu, q1, d + 3), sK[(d + 35) * AKW + lane], a3);
        }
        float s = bp[j] + ((a0 + a1) + (a2 + a3));
        float w = (j <= jmax) ? __expf(s - 20.f) : 0.f;
        lsum += w;
        #pragma unroll
        for (int l2 = 0; l2 < 32; l2++) {
            float wl = __shfl_sync(0xffffffffu, w, l2);
            o0 = fmaf(wl, sV[l2 * 64 + lane],      o0);
            o1 = fmaf(wl, sV[l2 * 64 + lane + 32], o1);
        }
        __syncthreads();
    }
    lsum = warpReduceSum(lsum);
    float inv = 1.f / lsum;
    o0 *= inv; o1 *= inv;
    size_t op = ((size_t)(b * NN + i)) * 512 + h * 64;
    __half h0 = __float2half_rn(o0);
    __half h1 = __float2half_rn(o1);
    g_Oh[op + lane]      = h0;  g_Ol[op + lane]      = __float2half_rn(o0 - __half2float(h0));
    g_Oh[op + lane + 32] = h1;  g_Ol[op + lane + 32] = __float2half_rn(o1 - __half2float(h1));
}

// ---------------- host orchestration --------------------------------------
static inline void run_gemm(const __half* Ah, const __half* Al, const __half* Bh,
                            const float* bias, float* C,
                            __half* outh, __half* outl,
                            int M, int N, int K, int mode) {
    dim3 grid(N / 128, (M + 63) / 64);
    bgemm_kernel<<<grid, 256, SMEM_TOT>>>(Ah, Al, Bh, bias, C, outh, outl, M, N, K, mode);
}

extern "C" void kernel_launch(void* const* d_in, const int* in_sizes, int n_in,
                              void* d_out, int out_size) {
    (void)in_sizes; (void)n_in; (void)out_size;
    const float* x            = (const float*)d_in[0];
    const float* attn_norm_g  = (const float*)d_in[1];
    const float* Wq           = (const float*)d_in[2];
    const float* Wkv          = (const float*)d_in[3];
    const float* bkv          = (const float*)d_in[4];
    const float* null_kv      = (const float*)d_in[5];
    const float* Wo           = (const float*)d_in[6];
    const float* out_norm_g   = (const float*)d_in[7];
    const float* ff_norm_g    = (const float*)d_in[8];
    const float* Wff1         = (const float*)d_in[9];
    const float* Wff2         = (const float*)d_in[10];
    const float* relpos       = (const float*)d_in[11];
    const float* final_norm_g = (const float*)d_in[12];
    const float* Wproj        = (const float*)d_in[13];
    float* out = (float*)d_out;

    cudaFuncSetAttribute(bgemm_kernel, cudaFuncAttributeMaxDynamicSharedMemorySize, SMEM_TOT);

    float *X, *QKV, *T, *BQKV;
    __half *XNh, *XNl, *Oh, *Ol, *AGh, *AGl;
    __half *WqkvT, *WoT, *W1T, *W2T, *WpT;
    cudaGetSymbolAddress((void**)&X,   g_X);
    cudaGetSymbolAddress((void**)&QKV, g_QKV);
    cudaGetSymbolAddress((void**)&T,   g_T);
    cudaGetSymbolAddress((void**)&BQKV, g_bqkv);
    cudaGetSymbolAddress((void**)&XNh, g_XNh); cudaGetSymbolAddress((void**)&XNl, g_XNl);
    cudaGetSymbolAddress((void**)&Oh,  g_Oh);  cudaGetSymbolAddress((void**)&Ol,  g_Ol);
    cudaGetSymbolAddress((void**)&AGh, g_AGh); cudaGetSymbolAddress((void**)&AGl, g_AGl);
    cudaGetSymbolAddress((void**)&WqkvT, g_WqkvT);
    cudaGetSymbolAddress((void**)&WoT, g_WoT);
    cudaGetSymbolAddress((void**)&W1T, g_Wff1T);
    cudaGetSymbolAddress((void**)&W2T, g_Wff2T);
    cudaGetSymbolAddress((void**)&WpT, g_WprojT);

    // launch 1: precompute
    precompute_kernel<<<(NN * NKV + 255) / 256, 256>>>(relpos, bkv);

    // launch 2: fused weight transpose
    WTable tab;
    int di = 0;
    for (int l = 0; l < LL; l++) {
        tab.d[di++] = { Wq   + (size_t)l * DD * 512,     WqkvT + (size_t)l * 640 * DD,            DD,  512,     0 };
        tab.d[di++] = { Wkv  + (size_t)l * DD * 128,     WqkvT + (size_t)l * 640 * DD + 512 * DD, DD,  128,     0 };
        tab.d[di++] = { Wo   + (size_t)l * 512 * DD,     WoT + (size_t)l * DD * 512,              512, DD,      0 };
        tab.d[di++] = { Wff1 + (size_t)l * DD * 2 * FFD, W1T + (size_t)l * 2 * FFD * DD,          DD,  2 * FFD, 1 };
        tab.d[di++] = { Wff2 + (size_t)l * FFD * DD,     W2T + (size_t)l * DD * FFD,              FFD, DD,      0 };
    }
    tab.d[di++] = { Wproj, WpT, DD, DD, 0 };
    tab.off[0] = 0;
    for (int i = 0; i < 21; i++)
        tab.off[i + 1] = tab.off[i] + (tab.d[i].N >> 5) * (tab.d[i].K >> 5);
    wsplit_all_kernel<<<tab.off[21], dim3(32, 8)>>>(tab);

    for (int l = 0; l < LL; l++) {
        if (l == 0) {
            ln_kernel<<<MM, 256>>>(x, attn_norm_g, XNh, XNl, 0);
        }
        run_gemm(XNh, XNl, WqkvT + (size_t)l * 640 * DD, BQKV + l * 640,
                 QKV, nullptr, nullptr, MM, 640, DD, 0);
        kvpost_kernel<<<(BB * NKV * 32 + 255) / 256, 256>>>(null_kv + (size_t)l * 128);
        attn_kernel<<<BB * NN, 256>>>();
        run_gemm(Oh, Ol, WoT + (size_t)l * DD * 512, nullptr, T, nullptr, nullptr, MM, DD, 512, 0);
        ln2_kernel<<<MM, 256>>>(T, (l == 0) ? x : X, out_norm_g + (size_t)l * DD,
                                ff_norm_g + (size_t)l * DD, X, XNh, XNl);
        run_gemm(XNh, XNl, W1T + (size_t)l * 2 * FFD * DD, nullptr, nullptr, AGh, AGl, MM, 2 * FFD, DD, 2);
        run_gemm(AGh, AGl, W2T + (size_t)l * DD * FFD, nullptr, X, nullptr, nullptr, MM, DD, FFD, 1);
        if (l + 1 < LL) {
            ln_kernel<<<MM, 256>>>(X, attn_norm_g + (size_t)(l + 1) * DD, XNh, XNl, 0);
        }
    }

    ln_kernel<<<MM, 256>>>(X, final_norm_g, XNh, XNl, 2);
    run_gemm(XNh, XNl, WpT, nullptr, out, nullptr, nullptr, MM, DD, DD, 0);
}

// round 16
// speedup vs baseline: 1.0680x; 1.0680x over previous
#include <cuda_runtime.h>
#include <cuda_fp16.h>
#include <math.h>
#include <float.h>
#include <stdint.h>

#define BB   8
#define NN   515
#define DD   1024
#define HH   8
#define LL   4
#define FFD  4096
#define NKV  516
#define MM   (BB*NN)
#define KTP  552
#define EPSL 1e-5f

// ---------------- scratch ----------------
__device__ float g_X  [MM*DD];
__device__ float g_QKV[MM*640];
__device__ float g_Kt [BB*64*KTP];
__device__ float g_V  [(BB*NKV + 32)*64];
__device__ float g_T  [MM*DD];
__device__ float g_bias[HH*NN*NKV + 64];
__device__ float g_bqkv[LL*640];
__device__ float g_cos[NN*16];
__device__ float g_sin[NN*16];
__device__ __half g_XNh[MM*DD],  g_XNl[MM*DD];
__device__ __half g_Oh [MM*512], g_Ol [MM*512];
__device__ __half g_AGh[(size_t)MM*FFD], g_AGl[(size_t)MM*FFD];
__device__ __half g_WqkvT[LL*640*DD];
__device__ __half g_WoT  [LL*DD*512];
__device__ __half g_Wff1T[(size_t)LL*2*FFD*DD];
__device__ __half g_Wff2T[(size_t)LL*DD*FFD];
__device__ __half g_WprojT[DD*DD];

// ---------------- small helpers ----------------
__device__ __forceinline__ uint32_t smem_u32(const void* p) {
    uint32_t a;
    asm("{ .reg .u64 t; cvta.to.shared.u64 t, %1; cvt.u32.u64 %0, t; }" : "=r"(a) : "l"(p));
    return a;
}
__device__ __forceinline__ void cp16(uint32_t dst, const void* src, bool pred) {
    int sz = pred ? 16 : 0;
    asm volatile("cp.async.cg.shared.global [%0], [%1], 16, %2;\n" :: "r"(dst), "l"(src), "r"(sz));
}
__device__ __forceinline__ void cp_commit() {
    asm volatile("cp.async.commit_group;\n" ::: "memory");
}
template<int N>
__device__ __forceinline__ void cp_wait() {
    asm volatile("cp.async.wait_group %0;\n" :: "n"(N) : "memory");
}
__device__ __forceinline__ void ldsm4(uint32_t* r, uint32_t addr) {
    asm volatile("ldmatrix.sync.aligned.m8n8.x4.shared.b16 {%0,%1,%2,%3}, [%4];"
                 : "=r"(r[0]), "=r"(r[1]), "=r"(r[2]), "=r"(r[3]) : "r"(addr));
}
__device__ __forceinline__ void mma_f16(float* c, const uint32_t* a, const uint32_t* b) {
    asm volatile(
        "mma.sync.aligned.m16n8k16.row.col.f32.f16.f16.f32 "
        "{%0,%1,%2,%3}, {%4,%5,%6,%7}, {%8,%9}, {%0,%1,%2,%3};"
        : "+f"(c[0]), "+f"(c[1]), "+f"(c[2]), "+f"(c[3])
        : "r"(a[0]), "r"(a[1]), "r"(a[2]), "r"(a[3]), "r"(b[0]), "r"(b[1]));
}

// ===== mma.sync 2-term fp16-split GEMM, templated CTA M-tile ===============
// BM=128 (occ2, warp tile 64x32) for B-reuse-bound GEMMs;
// BM=64  (occ3, warp tile 32x32) for latency-bound small-N GEMMs.
// k-chunk 64, stride-72 smem rows, 2-stage.
// Per-accumulator MMA order identical across BM and to rounds 8-15.
template<int BM, int OCC>
__global__ __launch_bounds__(256, OCC)
void bgemm_kernel(const __half* __restrict__ Ah, const __half* __restrict__ Al,
                  const __half* __restrict__ Bh,
                  const float* __restrict__ bias, float* __restrict__ C,
                  __half* __restrict__ outh, __half* __restrict__ outl,
                  int M, int N, int K, int mode)
{
    constexpr int MT   = BM / 32;           // m-subtiles per warp
    constexpr int A_HB = BM * 72 * 2;       // bytes per A tile (hi or lo)
    constexpr int B_HB = 128 * 72 * 2;
    constexpr int STG  = 2 * A_HB + B_HB;
    constexpr int AU   = 2 * BM * 8;        // A 16B-units per chunk (hi+lo)
    constexpr int TOT  = AU + 1024;

    extern __shared__ char smem[];
    const uint32_t sbase = smem_u32(smem);

    const int tid  = threadIdx.x;
    const int lane = tid & 31;
    const int warp = tid >> 5;
    const int warp_row = (warp & 1) * (BM / 2);
    const int warp_col = (warp >> 1) * 32;
    const int block_row = blockIdx.y * BM;
    const int block_col = blockIdx.x * 128;
    const int KC = K >> 6;

    const int aRow  = (lane & 15);
    const int aColH = (lane >> 4) << 3;
    const int bRow  = ((lane >> 4) << 3) + (lane & 7);
    const int bColH = ((lane >> 3) & 1) << 3;

    float acc[MT][4][4];
    #pragma unroll
    for (int a = 0; a < MT; a++)
        #pragma unroll
        for (int b = 0; b < 4; b++)
            #pragma unroll
            for (int c = 0; c < 4; c++) acc[a][b][c] = 0.f;

    auto load_chunk = [&](int s, int k0) {
        const uint32_t st = sbase + s * STG;
        #pragma unroll
        for (int i = 0; i < TOT / 256; i++) {
            const int u = tid + i * 256;
            if (u < AU) {
                const int v = u & (AU / 2 - 1);
                const int row = v >> 3, cc = (v & 7) * 8;
                const int gr = block_row + row;
                const __half* src = ((u < AU / 2) ? Ah : Al) + (size_t)gr * K + k0 + cc;
                cp16(st + ((u < AU / 2) ? 0 : A_HB) + (row * 72 + cc) * 2, src, gr < M);
            } else {
                const int v = u - AU;
                const int row = v >> 3, cc = (v & 7) * 8;
                cp16(st + 2 * A_HB + (row * 72 + cc) * 2,
                     Bh + (size_t)(block_col + row) * K + k0 + cc, true);
            }
        }
        cp_commit();
    };

    load_chunk(0, 0);

    for (int c = 0; c < KC; ++c) {
        const int s = c & 1;
        if (c + 1 < KC) {
            load_chunk(s ^ 1, (c + 1) << 6);
            cp_wait<1>();
        } else {
            cp_wait<0>();
        }
        __syncthreads();

        const uint32_t st = sbase + s * STG;
        #pragma unroll
        for (int ks = 0; ks < 4; ks++) {
            const int k0s = ks << 4;
            uint32_t ah[MT][4], al[MT][4], bh[2][4];
            #pragma unroll
            for (int mt = 0; mt < MT; mt++) {
                const uint32_t addr = st + ((warp_row + mt * 16 + aRow) * 72 + k0s + aColH) * 2;
                ldsm4(ah[mt], addr);
                ldsm4(al[mt], addr + A_HB);
            }
            #pragma unroll
            for (int np = 0; np < 2; np++) {
                const uint32_t addr = st + 2 * A_HB +
                    ((warp_col + np * 16 + bRow) * 72 + k0s + bColH) * 2;
                ldsm4(bh[np], addr);
            }
            #pragma unroll
            for (int mt = 0; mt < MT; mt++)
                #pragma unroll
                for (int nt = 0; nt < 4; nt++)
                    mma_f16(acc[mt][nt], ah[mt], &bh[nt >> 1][(nt & 1) * 2]);
            #pragma unroll
            for (int mt = 0; mt < MT; mt++)
                #pragma unroll
                for (int nt = 0; nt < 4; nt++)
                    mma_f16(acc[mt][nt], al[mt], &bh[nt >> 1][(nt & 1) * 2]);
        }
        __syncthreads();
    }

    const int gid = lane >> 2;
    const int tig = lane & 3;
    #pragma unroll
    for (int mt = 0; mt < MT; mt++) {
        int r0 = block_row + warp_row + mt * 16 + gid;
        #pragma unroll
        for (int half = 0; half < 2; half++) {
            int r = r0 + half * 8;
            if (r >= M) continue;
            #pragma unroll
            for (int nt = 0; nt < 4; nt++) {
                int col = block_col + warp_col + nt * 8 + 2 * tig;
                float v0 = acc[mt][nt][half * 2 + 0];
                float v1 = acc[mt][nt][half * 2 + 1];
                if (mode == 2) {
                    float v = v0 * v1 / (1.f + __expf(-v1));
                    __half h = __float2half_rn(v);
                    size_t o = (size_t)r * (N >> 1) + (col >> 1);
                    outh[o] = h;
                    outl[o] = __float2half_rn(v - __half2float(h));
                } else {
                    if (bias) { v0 += bias[col]; v1 += bias[col + 1]; }
                    float* cp = C + (size_t)r * N + col;
                    if (mode == 1) { cp[0] += v0; cp[1] += v1; }
                    else           { cp[0]  = v0; cp[1]  = v1; }
                }
            }
        }
    }
}

#define SMEM128  (2*(3*128*72*2))      // 110592
#define SMEM64   (2*(2*64*72*2 + 128*72*2))  // 73728

// -------- fused weight transpose (fp16, one launch, tight grid) ------------
struct WDesc { const float* W; __half* Th; int K; int N; int glu; };
struct WTable { WDesc d[21]; int off[22]; };

__global__ void wsplit_all_kernel(WTable tab) {
    const int bid = blockIdx.x;
    int wi = 0;
    while (bid >= tab.off[wi + 1]) wi++;
    const WDesc w = tab.d[wi];
    const int t = bid - tab.off[wi];
    const int tilesN = w.N >> 5;
    const int nb = (t % tilesN) * 32;
    const int kb = (t / tilesN) * 32;
    __shared__ float sm[32][33];
    const int x = threadIdx.x, y = threadIdx.y;
    const int n0 = nb + x;
    const int sc = w.glu ? ((n0 & 1) * FFD + (n0 >> 1)) : n0;
    #pragma unroll
    for (int j = 0; j < 32; j += 8)
        sm[y + j][x] = w.W[(size_t)(kb + y + j) * w.N + sc];
    __syncthreads();
    #pragma unroll
    for (int j = 0; j < 32; j += 8)
        w.Th[(size_t)(nb + y + j) * w.K + kb + x] = __float2half_rn(sm[x][y + j]);
}

// ---------------- reductions ----------------
__device__ __forceinline__ float warpReduceSum(float v) {
    #pragma unroll
    for (int o = 16; o > 0; o >>= 1) v += __shfl_xor_sync(0xffffffffu, v, o);
    return v;
}
__device__ __forceinline__ float warpReduceMax(float v) {
    #pragma unroll
    for (int o = 16; o > 0; o >>= 1) v = fmaxf(v, __shfl_xor_sync(0xffffffffu, v, o));
    return v;
}
__device__ __forceinline__ float blockReduceSum(float v) {
    __shared__ float sh[8];
    int lane = threadIdx.x & 31, w = threadIdx.x >> 5;
    v = warpReduceSum(v);
    __syncthreads();
    if (lane == 0) sh[w] = v;
    __syncthreads();
    if (w == 0) {
        float t = (lane < 8) ? sh[lane] : 0.f;
        t = warpReduceSum(t);
        if (lane == 0) sh[0] = t;
    }
    __syncthreads();
    return sh[0];
}
__device__ __forceinline__ float blockReduceMax(float v) {
    __shared__ float sh[8];
    int lane = threadIdx.x & 31, w = threadIdx.x >> 5;
    v = warpReduceMax(v);
    __syncthreads();
    if (lane == 0) sh[w] = v;
    __syncthreads();
    if (w == 0) {
        float t = (lane < 8) ? sh[lane] : -FLT_MAX;
        t = warpReduceMax(t);
        if (lane == 0) sh[0] = t;
    }
    __syncthreads();
    return sh[0];
}

// -------- LayerNorm: mode 0 split(LN(in)*g), mode 2 stable split ------------
__global__ __launch_bounds__(256)
void ln_kernel(const float* __restrict__ in, const float* __restrict__ g,
               __half* __restrict__ outh, __half* __restrict__ outl, int mode)
{
    const int row = blockIdx.x;
    const float* xr = in + (size_t)row * DD;
    const int t = threadIdx.x;
    float v[4];
    #pragma unroll
    for (int i = 0; i < 4; i++) v[i] = xr[t + i * 256];
    if (mode == 2) {
        float lm = -FLT_MAX;
        #pragma unroll
        for (int i = 0; i < 4; i++) lm = fmaxf(lm, v[i]);
        float inv = 1.f / blockReduceMax(lm);
        #pragma unroll
        for (int i = 0; i < 4; i++) v[i] *= inv;
    }
    float s = 0.f;
    #pragma unroll
    for (int i = 0; i < 4; i++) s += v[i];
    float mean = blockReduceSum(s) * (1.f / DD);
    float vs = 0.f;
    #pragma unroll
    for (int i = 0; i < 4; i++) { float d = v[i] - mean; vs += d * d; }
    float rstd = rsqrtf(blockReduceSum(vs) * (1.f / DD) + EPSL);
    #pragma unroll
    for (int i = 0; i < 4; i++) {
        int c = t + i * 256;
        float y = (v[i] - mean) * rstd * g[c];
        size_t idx = (size_t)row * DD + c;
        __half h = __float2half_rn(y);
        outh[idx] = h;
        outl[idx] = __float2half_rn(y - __half2float(h));
    }
}

// -------- fused: X = resid + LN(T)*g1 ; split(LN(X)*g2) --------------------
__global__ __launch_bounds__(256)
void ln2_kernel(const float* __restrict__ T, const float* __restrict__ resid,
                const float* __restrict__ g1, const float* __restrict__ g2,
                float* __restrict__ X, __half* __restrict__ outh,
                __half* __restrict__ outl)
{
    const int row = blockIdx.x;
    const int t = threadIdx.x;
    const float* tr = T + (size_t)row * DD;
    const float* rr = resid + (size_t)row * DD;
    float v[4];
    #pragma unroll
    for (int i = 0; i < 4; i++) v[i] = tr[t + i * 256];
    float s = 0.f;
    #pragma unroll
    for (int i = 0; i < 4; i++) s += v[i];
    float mean = blockReduceSum(s) * (1.f / DD);
    float vs = 0.f;
    #pragma unroll
    for (int i = 0; i < 4; i++) { float d = v[i] - mean; vs += d * d; }
    float rstd = rsqrtf(blockReduceSum(vs) * (1.f / DD) + EPSL);
    float x[4];
    #pragma unroll
    for (int i = 0; i < 4; i++) {
        int c = t + i * 256;
        x[i] = rr[c] + (v[i] - mean) * rstd * g1[c];
        X[(size_t)row * DD + c] = x[i];
    }
    float s2 = 0.f;
    #pragma unroll
    for (int i = 0; i < 4; i++) s2 += x[i];
    float mean2 = blockReduceSum(s2) * (1.f / DD);
    float vs2 = 0.f;
    #pragma unroll
    for (int i = 0; i < 4; i++) { float d = x[i] - mean2; vs2 += d * d; }
    float rstd2 = rsqrtf(blockReduceSum(vs2) * (1.f / DD) + EPSL);
    #pragma unroll
    for (int i = 0; i < 4; i++) {
        int c = t + i * 256;
        float y = (x[i] - mean2) * rstd2 * g2[c];
        size_t idx = (size_t)row * DD + c;
        __half h = __float2half_rn(y);
        outh[idx] = h;
        outl[idx] = __float2half_rn(y - __half2float(h));
    }
}

// ---------------- precompute: rope + rel-pos bias + qkv bias ---------------
__global__ void precompute_kernel(const float* __restrict__ emb,
                                  const float* __restrict__ bkv) {
    int idx = blockIdx.x * blockDim.x + threadIdx.x;
    if (idx < NN * 16) {
        int p = idx >> 4, i = idx & 15;
        float fr = (float)p * powf(10000.f, -(float)(2 * i) / 32.f);
        g_cos[idx] = cosf(fr);
        g_sin[idx] = sinf(fr);
    }
    if (idx < LL * 640) {
        int c = idx % 640;
        g_bqkv[idx] = (c < 512) ? 0.f : bkv[(idx / 640) * 128 + c - 512];
    }
    if (idx >= NN * NKV) return;
    int i = idx / NKV, j = idx % NKV;
    int nn = max(i - j, 0);
    int bucket;
    if (nn < 16) bucket = nn;
    else {
        int vl = 16 + (int)(logf((float)nn * (1.f / 16.f)) / logf(8.f) * 16.f);
        bucket = min(vl, 31);
    }
    #pragma unroll
    for (int h = 0; h < HH; h++)
        g_bias[((size_t)h * NN + i) * NKV + j] = emb[bucket * HH + h];
}

// ---------------- kv post: rotary+norm k -> Kt, copy v ----------------------
__global__ __launch_bounds__(256)
void kvpost_kernel(const float* __restrict__ nullkv) {
    int gw   = (blockIdx.x * blockDim.x + threadIdx.x) >> 5;
    int lane = threadIdx.x & 31;
    if (gw >= BB * NKV) return;
    int b = gw / NKV, j = gw % NKV;
    float k0, k1, v0, v1;
    if (j == 0) {
        k0 = nullkv[lane];      k1 = nullkv[lane + 32];
        v0 = nullkv[64 + lane]; v1 = nullkv[96 + lane];
    } else {
        int pos = j - 1;
        const float* kv = g_QKV + ((size_t)(b * NN + pos)) * 640 + 512;
        k0 = kv[lane];      k1 = kv[lane + 32];
        v0 = kv[64 + lane]; v1 = kv[96 + lane];
        float c = g_cos[pos * 16 + (lane >> 1)];
        float s = g_sin[pos * 16 + (lane >> 1)];
        float part = __shfl_xor_sync(0xffffffffu, k0, 1);
        k0 = (lane & 1) ? fmaf(k0, c, part * s) : fmaf(k0, c, -part * s);
    }
    float inv = 4.f * rsqrtf(warpReduceSum(k0 * k0 + k1 * k1));
    g_Kt[((size_t)b * 64 + lane)      * KTP + j] = k0 * inv;
    g_Kt[((size_t)b * 64 + lane + 32) * KTP + j] = k1 * inv;
    size_t o = ((size_t)(b * NKV + j)) * 64;
    g_V[o + lane] = v0;
    g_V[o + lane + 32] = v1;
}

// -------- attention: block per (b,i) LPT-ordered, warp per head ------------
#define AKW   36
#define ASTG  (64*AKW + 32*64)
__global__ __launch_bounds__(256)
void attn_kernel() {
    __shared__ float sbuf[2 * ASTG];
    // LPT: longest blocks (largest i) first
    const int b = blockIdx.x & 7;
    const int i = NN - 1 - (blockIdx.x >> 3);
    const int h = threadIdx.x >> 5;
    const int lane = threadIdx.x & 31;

    const float* qp = g_QKV + ((size_t)(b * NN + i)) * 640 + h * 64;
    float q0 = qp[lane], q1 = qp[lane + 32];
    {
        float c = g_cos[i * 16 + (lane >> 1)];
        float s = g_sin[i * 16 + (lane >> 1)];
        float part = __shfl_xor_sync(0xffffffffu, q0, 1);
        q0 = (lane & 1) ? fmaf(q0, c, part * s) : fmaf(q0, c, -part * s);
        float inv = 4.f * rsqrtf(warpReduceSum(q0 * q0 + q1 * q1));
        q0 *= inv; q1 *= inv;
    }
    const float* Ktb = g_Kt + (size_t)b * 64 * KTP;
    const float* Vb  = g_V  + (size_t)b * NKV * 64;
    const float* bp  = g_bias + ((size_t)h * NN + i) * NKV;
    const uint32_t sb = smem_u32(sbuf);

    auto load_blk = [&](int s, int j0) {
        const uint32_t st = sb + s * (ASTG * 4);
        #pragma unroll
        for (int t = 0; t < 4; t++) {
            const int u = threadIdx.x + t * 256;
            if (u < 512) {
                const int d = u >> 3, uu = (u & 7) * 4;
                cp16(st + (d * AKW + uu) * 4, Ktb + (size_t)d * KTP + j0 + uu, true);
            } else {
                const int v = u - 512;
                const int row = v >> 4, uu = (v & 15) * 4;
                cp16(st + (64 * AKW + row * 64 + uu) * 4,
                     Vb + (size_t)(j0 + row) * 64 + uu, true);
            }
        }
        cp_commit();
    };

    const int jmax = i + 1;
    const int NBK = (jmax >> 5) + 1;
    load_blk(0, 0);

    float lsum = 0.f, o0 = 0.f, o1 = 0.f;
    for (int blk = 0; blk < NBK; blk++) {
        if (blk + 1 < NBK) {
            load_blk((blk + 1) & 1, (blk + 1) << 5);
            cp_wait<1>();
        } else {
            cp_wait<0>();
        }
        __syncthreads();

        const float* sK = sbuf + (blk & 1) * ASTG;
        const float* sV = sK + 64 * AKW;
        const int j = (blk << 5) + lane;

        float a0 = 0.f, a1 = 0.f, a2 = 0.f, a3 = 0.f;
        #pragma unroll
        for (int d = 0; d < 32; d += 4) {
            a0 = fmaf(__shfl_sync(0xffffffffu, q0, d    ), sK[(d    ) * AKW + lane], a0);
            a1 = fmaf(__shfl_sync(0xffffffffu, q0, d + 1), sK[(d + 1) * AKW + lane], a1);
            a2 = fmaf(__shfl_sync(0xffffffffu, q0, d + 2), sK[(d + 2) * AKW + lane], a2);
            a3 = fmaf(__shfl_sync(0xffffffffu, q0, d + 3), sK[(d + 3) * AKW + lane], a3);
        }
        #pragma unroll
        for (int d = 0; d < 32; d += 4) {
            a0 = fmaf(__shfl_sync(0xffffffffu, q1, d    ), sK[(d + 32) * AKW + lane], a0);
            a1 = fmaf(__shfl_sync(0xffffffffu, q1, d + 1), sK[(d + 33) * AKW + lane], a1);
            a2 = fmaf(__shfl_sync(0xffffffffu, q1, d + 2), sK[(d + 34) * AKW + lane], a2);
            a3 = fmaf(__shfl_sync(0xffffffffu, q1, d + 3), sK[(d + 35) * AKW + lane], a3);
        }
        float s = bp[j] + ((a0 + a1) + (a2 + a3));
        float w = (j <= jmax) ? __expf(s - 20.f) : 0.f;
        lsum += w;
        #pragma unroll
        for (int l2 = 0; l2 < 32; l2++) {
            float wl = __shfl_sync(0xffffffffu, w, l2);
            o0 = fmaf(wl, sV[l2 * 64 + lane],      o0);
            o1 = fmaf(wl, sV[l2 * 64 + lane + 32], o1);
        }
        __syncthreads();
    }
    lsum = warpReduceSum(lsum);
    float inv = 1.f / lsum;
    o0 *= inv; o1 *= inv;
    size_t op = ((size_t)(b * NN + i)) * 512 + h * 64;
    __half h0 = __float2half_rn(o0);
    __half h1 = __float2half_rn(o1);
    g_Oh[op + lane]      = h0;  g_Ol[op + lane]      = __float2half_rn(o0 - __half2float(h0));
    g_Oh[op + lane + 32] = h1;  g_Ol[op + lane + 32] = __float2half_rn(o1 - __half2float(h1));
}

// ---------------- host orchestration --------------------------------------
static inline void run_gemm(const __half* Ah, const __half* Al, const __half* Bh,
                            const float* bias, float* C,
                            __half* outh, __half* outl,
                            int M, int N, int K, int mode) {
    if (N == 640) {
        dim3 grid(N / 128, (M + 63) / 64);
        bgemm_kernel<64, 3><<<grid, 256, SMEM64>>>(Ah, Al, Bh, bias, C, outh, outl, M, N, K, mode);
    } else {
        dim3 grid(N / 128, (M + 127) / 128);
        bgemm_kernel<128, 2><<<grid, 256, SMEM128>>>(Ah, Al, Bh, bias, C, outh, outl, M, N, K, mode);
    }
}

extern "C" void kernel_launch(void* const* d_in, const int* in_sizes, int n_in,
                              void* d_out, int out_size) {
    (void)in_sizes; (void)n_in; (void)out_size;
    const float* x            = (const float*)d_in[0];
    const float* attn_norm_g  = (const float*)d_in[1];
    const float* Wq           = (const float*)d_in[2];
    const float* Wkv          = (const float*)d_in[3];
    const float* bkv          = (const float*)d_in[4];
    const float* null_kv      = (const float*)d_in[5];
    const float* Wo           = (const float*)d_in[6];
    const float* out_norm_g   = (const float*)d_in[7];
    const float* ff_norm_g    = (const float*)d_in[8];
    const float* Wff1         = (const float*)d_in[9];
    const float* Wff2         = (const float*)d_in[10];
    const float* relpos       = (const float*)d_in[11];
    const float* final_norm_g = (const float*)d_in[12];
    const float* Wproj        = (const float*)d_in[13];
    float* out = (float*)d_out;

    cudaFuncSetAttribute((const void*)bgemm_kernel<128, 2>,
                         cudaFuncAttributeMaxDynamicSharedMemorySize, SMEM128);
    cudaFuncSetAttribute((const void*)bgemm_kernel<64, 3>,
                         cudaFuncAttributeMaxDynamicSharedMemorySize, SMEM64);

    float *X, *QKV, *T, *BQKV;
    __half *XNh, *XNl, *Oh, *Ol, *AGh, *AGl;
    __half *WqkvT, *WoT, *W1T, *W2T, *WpT;
    cudaGetSymbolAddress((void**)&X,   g_X);
    cudaGetSymbolAddress((void**)&QKV, g_QKV);
    cudaGetSymbolAddress((void**)&T,   g_T);
    cudaGetSymbolAddress((void**)&BQKV, g_bqkv);
    cudaGetSymbolAddress((void**)&XNh, g_XNh); cudaGetSymbolAddress((void**)&XNl, g_XNl);
    cudaGetSymbolAddress((void**)&Oh,  g_Oh);  cudaGetSymbolAddress((void**)&Ol,  g_Ol);
    cudaGetSymbolAddress((void**)&AGh, g_AGh); cudaGetSymbolAddress((void**)&AGl, g_AGl);
    cudaGetSymbolAddress((void**)&WqkvT, g_WqkvT);
    cudaGetSymbolAddress((void**)&WoT, g_WoT);
    cudaGetSymbolAddress((void**)&W1T, g_Wff1T);
    cudaGetSymbolAddress((void**)&W2T, g_Wff2T);
    cudaGetSymbolAddress((void**)&WpT, g_WprojT);

    // launch 1: precompute
    precompute_kernel<<<(NN * NKV + 255) / 256, 256>>>(relpos, bkv);

    // launch 2: fused weight transpose
    WTable tab;
    int di = 0;
    for (int l = 0; l < LL; l++) {
        tab.d[di++] = { Wq   + (size_t)l * DD * 512,     WqkvT + (size_t)l * 640 * DD,            DD,  512,     0 };
        tab.d[di++] = { Wkv  + (size_t)l * DD * 128,     WqkvT + (size_t)l * 640 * DD + 512 * DD, DD,  128,     0 };
        tab.d[di++] = { Wo   + (size_t)l * 512 * DD,     WoT + (size_t)l * DD * 512,              512, DD,      0 };
        tab.d[di++] = { Wff1 + (size_t)l * DD * 2 * FFD, W1T + (size_t)l * 2 * FFD * DD,          DD,  2 * FFD, 1 };
        tab.d[di++] = { Wff2 + (size_t)l * FFD * DD,     W2T + (size_t)l * DD * FFD,              FFD, DD,      0 };
    }
    tab.d[di++] = { Wproj, WpT, DD, DD, 0 };
    tab.off[0] = 0;
    for (int i = 0; i < 21; i++)
        tab.off[i + 1] = tab.off[i] + (tab.d[i].N >> 5) * (tab.d[i].K >> 5);
    wsplit_all_kernel<<<tab.off[21], dim3(32, 8)>>>(tab);

    for (int l = 0; l < LL; l++) {
        if (l == 0) {
            ln_kernel<<<MM, 256>>>(x, attn_norm_g, XNh, XNl, 0);
        }
        run_gemm(XNh, XNl, WqkvT + (size_t)l * 640 * DD, BQKV + l * 640,
                 QKV, nullptr, nullptr, MM, 640, DD, 0);
        kvpost_kernel<<<(BB * NKV * 32 + 255) / 256, 256>>>(null_kv + (size_t)l * 128);
        attn_kernel<<<BB * NN, 256>>>();
        run_gemm(Oh, Ol, WoT + (size_t)l * DD * 512, nullptr, T, nullptr, nullptr, MM, DD, 512, 0);
        ln2_kernel<<<MM, 256>>>(T, (l == 0) ? x : X, out_norm_g + (size_t)l * DD,
                                ff_norm_g + (size_t)l * DD, X, XNh, XNl);
        run_gemm(XNh, XNl, W1T + (size_t)l * 2 * FFD * DD, nullptr, nullptr, AGh, AGl, MM, 2 * FFD, DD, 2);
        run_gemm(AGh, AGl, W2T + (size_t)l * DD * FFD, nullptr, X, nullptr, nullptr, MM, DD, FFD, 1);
        if (l + 1 < LL) {
            ln_kernel<<<MM, 256>>>(X, attn_norm_g + (size_t)(l + 1) * DD, XNh, XNl, 0);
        }
    }

    ln_kernel<<<MM, 256>>>(X, final_norm_g, XNh, XNl, 2);
    run_gemm(XNh, XNl, WpT, nullptr, out, nullptr, nullptr, MM, DD, DD, 0);
}